// round 10
// baseline (speedup 1.0000x reference)
#include <cuda_runtime.h>

// Problem constants
#define BATCH 8
#define NCLS 19
#define HH 768
#define WW 768
#define HWP (HH * WW)                 // 589824
#define N_PIX (BATCH * HWP)           // 4718592
#define N4 (N_PIX / 4)                // 1179648
#define IGNORE_LBL 255
#define MIN_KEPT_K 262144u
#define THRESH_F 0.7f
#define ONE_BITS 0x3F800000u
#define ALMOST_ONE_BITS 0x3F7FFFFFu
#define MAIN_BLOCKS 1184
#define MAIN_STRIDE (MAIN_BLOCKS * 256)   // 303104 < HWP

// Scratch (no cudaMalloc allowed). Globals are zero at module load; the
// kernel self-restores all state it consumes, so replays are deterministic.
__device__ float g_prob[N_PIX];                // rare path only
__device__ unsigned int g_h16[65536];          // rare path only (zeroed there)
__device__ unsigned int g_num_valid;
__device__ unsigned int g_c07;
__device__ double g_sum07;
__device__ double g_sumall;
__device__ unsigned int g_done_main;

// ---------------------------------------------------------------------------
__device__ __forceinline__ float encode_prob(float logp, bool valid) {
    if (!valid) return 1.0f;
    float pr = __expf(logp);
    unsigned int bb = __float_as_uint(pr);
    if (bb >= ONE_BITS) bb = ALMOST_ONE_BITS;   // 1.0f bits reserved for invalid
    return __uint_as_float(bb);
}

// Single-block (256-thread) inclusive scan over shared 256-bin histogram;
// returns this thread's inclusive sum (shared array left as scanned values).
__device__ __forceinline__ unsigned int scan256_shared(unsigned int* s) {
    int t = threadIdx.x;
#pragma unroll
    for (int o = 1; o < 256; o <<= 1) {
        unsigned int v = (t >= o) ? s[t - o] : 0u;
        __syncthreads();
        s[t] += v;
        __syncthreads();
    }
    return s[t];
}

// ---------------------------------------------------------------------------
// ONE kernel: fused log-softmax + common-path reductions (all blocks), then
// the last surviving block finishes: common case => write scalar; rare case
// (threshold > 0.7 needed) => full single-block radix-select + reduce.
// Rare path is correctness-only (never taken when >= MIN_KEPT valid pixels
// have gt-prob <= 0.7, which random logits always satisfy).
__global__ void __launch_bounds__(256) ohem_kernel(const float* __restrict__ pred,
                                                   const int* __restrict__ target,
                                                   float* __restrict__ out) {
    unsigned int vcnt = 0, c07 = 0;
    float lsum07 = 0.0f, lsumall = 0.0f;

    int i0 = blockIdx.x * blockDim.x + threadIdx.x;
    {
        int b = i0 / HWP;              // single divide; then incremental carry
        int hw = i0 - b * HWP;

        for (int i = i0; i < N_PIX; i += MAIN_STRIDE) {
            int t = __ldcs(target + i);
            bool valid = (t != IGNORE_LBL);
            int tc = valid ? t : 0;

            const float* p = pred + (size_t)b * (NCLS * HWP) + hw;
            float s0 = 0.0f, s1 = 0.0f, s2 = 0.0f, s3 = 0.0f;
            float vt = 0.0f;
#pragma unroll
            for (int c = 0; c < NCLS; c++) {
                float x = __ldcs(p + c * HWP);
                if (c == tc) vt = x;      // predicated select, no dynamic indexing
                if ((c & 3) == 0) s0 += __expf(x);
                else if ((c & 3) == 1) s1 += __expf(x);
                else if ((c & 3) == 2) s2 += __expf(x);
                else s3 += __expf(x);
            }
            float logp = vt - __logf((s0 + s1) + (s2 + s3));   // logits bounded
            float pr = encode_prob(logp, valid);

            bool kept07 = valid && (pr <= THRESH_F);
            vcnt += valid ? 1u : 0u;
            c07  += kept07 ? 1u : 0u;
            lsumall += valid ? -logp : 0.0f;
            lsum07  += kept07 ? -logp : 0.0f;

            hw += MAIN_STRIDE;
            if (hw >= HWP) { hw -= HWP; b++; }
        }
    }

    // block-reduce 2 uints + 2 floats
    __shared__ unsigned int sh[32], sh2[32];
    __shared__ float sf[32], sf2[32];
    int lane = threadIdx.x & 31, wid = threadIdx.x >> 5;
#pragma unroll
    for (int o = 16; o; o >>= 1) {
        vcnt += __shfl_down_sync(0xffffffffu, vcnt, o);
        c07  += __shfl_down_sync(0xffffffffu, c07, o);
        lsum07 += __shfl_down_sync(0xffffffffu, lsum07, o);
        lsumall += __shfl_down_sync(0xffffffffu, lsumall, o);
    }
    if (lane == 0) { sh[wid] = vcnt; sh2[wid] = c07; sf[wid] = lsum07; sf2[wid] = lsumall; }
    __syncthreads();
    if (wid == 0) {
        unsigned int v = (lane < 8) ? sh[lane] : 0u;
        unsigned int w = (lane < 8) ? sh2[lane] : 0u;
        float f1 = (lane < 8) ? sf[lane] : 0.0f;
        float f2 = (lane < 8) ? sf2[lane] : 0.0f;
#pragma unroll
        for (int o = 16; o; o >>= 1) {
            v += __shfl_down_sync(0xffffffffu, v, o);
            w += __shfl_down_sync(0xffffffffu, w, o);
            f1 += __shfl_down_sync(0xffffffffu, f1, o);
            f2 += __shfl_down_sync(0xffffffffu, f2, o);
        }
        if (lane == 0) {
            atomicAdd(&g_num_valid, v);
            atomicAdd(&g_c07, w);
            atomicAdd(&g_sum07, (double)f1);
            atomicAdd(&g_sumall, (double)f2);
        }
    }

    // -------- last surviving block finishes the job --------
    __shared__ bool is_last;
    if (threadIdx.x == 0) {
        __threadfence();
        is_last = (atomicAdd(&g_done_main, 1u) == gridDim.x - 1);
    }
    __syncthreads();
    if (!is_last) return;

    __shared__ unsigned int decision;   // 0 = done, 1 = need refinement
    __shared__ unsigned int s_nv;
    if (threadIdx.x == 0) {
        unsigned int nv = g_num_valid;
        unsigned int c07v = g_c07;
        s_nv = nv;
        bool do_ohem = (nv >= MIN_KEPT_K);
        if (!do_ohem) {
            unsigned int d = nv < 1u ? 1u : nv;
            out[0] = (float)(g_sumall / (double)d);
            decision = 0u;
        } else if (c07v >= MIN_KEPT_K) {    // kth <= 0.7 => threshold == 0.7
            unsigned int d = c07v < 1u ? 1u : c07v;
            out[0] = (float)(g_sum07 / (double)d);
            decision = 0u;
        } else {
            decision = 1u;
        }
        // reset state for next launch (replay-deterministic)
        g_num_valid = 0u; g_c07 = 0u;
        g_sum07 = 0.0; g_sumall = 0.0;
        g_done_main = 0u;
    }
    __syncthreads();
    if (decision == 0u) return;

    // ======== RARE PATH: single-block exact radix select + reduce ========
    // (correctness-only; never taken for this input distribution)
    const int t = threadIdx.x;
    __shared__ unsigned int shh[256];

    // pass 1: recompute prob for all pixels, store, exponent hist
    shh[t] = 0u;
    __syncthreads();
    {
        int b = 0, hw = t;
        for (int i = t; i < N_PIX; i += 256) {
            int tg = target[i];
            bool valid = (tg != IGNORE_LBL);
            int tc = valid ? tg : 0;
            const float* p = pred + (size_t)b * (NCLS * HWP) + hw;
            float sa = 0.0f, sb = 0.0f;
            float vt = 0.0f;
#pragma unroll
            for (int c = 0; c < NCLS; c++) {
                float x = p[c * HWP];
                if (c == tc) vt = x;
                if (c & 1) sb += __expf(x); else sa += __expf(x);
            }
            float pr = encode_prob(vt - __logf(sa + sb), valid);
            g_prob[i] = pr;
            atomicAdd(&shh[__float_as_uint(pr) >> 24], 1u);
            hw += 256;
            if (hw >= HWP) { hw -= HWP; b++; }
        }
    }
    __syncthreads();

    // scan round 1
    __shared__ unsigned int s_prefix, s_k;
    {
        unsigned int cc = shh[t];
        unsigned int incl = scan256_shared(shh);
        unsigned int excl = incl - cc;
        if (excl < MIN_KEPT_K && MIN_KEPT_K <= incl) {
            s_prefix = ((unsigned int)t) << 24;
            s_k = MIN_KEPT_K - excl;
        }
    }
    __syncthreads();

    // round 2: bits 23..8 filtered on hi-8 prefix (global 64K bins)
    for (int i = t; i < 65536; i += 256) g_h16[i] = 0u;
    __syncthreads();
    {
        unsigned int prefix = s_prefix;
        const uint4* p4u = reinterpret_cast<const uint4*>(g_prob);
        for (int i = t; i < N4; i += 256) {
            uint4 v = p4u[i];
            if ((v.x & 0xFF000000u) == prefix) atomicAdd(&g_h16[(v.x >> 8) & 0xFFFFu], 1u);
            if ((v.y & 0xFF000000u) == prefix) atomicAdd(&g_h16[(v.y >> 8) & 0xFFFFu], 1u);
            if ((v.z & 0xFF000000u) == prefix) atomicAdd(&g_h16[(v.z >> 8) & 0xFFFFu], 1u);
            if ((v.w & 0xFF000000u) == prefix) atomicAdd(&g_h16[(v.w >> 8) & 0xFFFFu], 1u);
        }
    }
    __syncthreads();
    {
        // per-thread partial sums over 256 bins each, then scan
        int base = t * 256;
        unsigned int lsum = 0;
        const uint4* h4 = reinterpret_cast<const uint4*>(g_h16);
        for (int j = 0; j < 64; j++) {
            uint4 u = h4[(base >> 2) + j];
            lsum += u.x + u.y + u.z + u.w;
        }
        shh[t] = lsum;
        __syncthreads();
        unsigned int incl = scan256_shared(shh);
        unsigned int excl = incl - lsum;
        unsigned int kk = s_k;
        if (excl < kk && kk <= incl && lsum > 0) {
            unsigned int cum = excl;
            for (int b2 = 0; b2 < 256; b2++) {
                unsigned int c = g_h16[base + b2];
                cum += c;
                if (cum >= kk) {
                    s_prefix = s_prefix | (((unsigned int)(base + b2)) << 8);
                    s_k = kk - (cum - c);
                    break;
                }
            }
        }
    }
    __syncthreads();

    // round 3: bits 7..0 filtered on hi-24 prefix
    __shared__ unsigned int s_kth;
    shh[t] = 0u;
    __syncthreads();
    {
        unsigned int prefix = s_prefix;
        const uint4* p4u = reinterpret_cast<const uint4*>(g_prob);
        for (int i = t; i < N4; i += 256) {
            uint4 v = p4u[i];
            if ((v.x & 0xFFFFFF00u) == prefix) atomicAdd(&shh[v.x & 255u], 1u);
            if ((v.y & 0xFFFFFF00u) == prefix) atomicAdd(&shh[v.y & 255u], 1u);
            if ((v.z & 0xFFFFFF00u) == prefix) atomicAdd(&shh[v.z & 255u], 1u);
            if ((v.w & 0xFFFFFF00u) == prefix) atomicAdd(&shh[v.w & 255u], 1u);
        }
    }
    __syncthreads();
    {
        unsigned int cc = shh[t];
        unsigned int incl = scan256_shared(shh);
        unsigned int excl = incl - cc;
        unsigned int kk = s_k;
        if (excl < kk && kk <= incl) {
            s_kth = s_prefix | (unsigned int)t;
        }
    }
    __syncthreads();

    // final reduce over g_prob (do_ohem true on this path)
    {
        float thr = fmaxf(__uint_as_float(s_kth), THRESH_F);
        float lsum = 0.0f;
        unsigned int cnt = 0;
        const float4* p4 = reinterpret_cast<const float4*>(g_prob);
        for (int i = t; i < N4; i += 256) {
            float4 v = p4[i];
            float pr[4] = {v.x, v.y, v.z, v.w};
#pragma unroll
            for (int e = 0; e < 4; e++) {
                bool valid = (__float_as_uint(pr[e]) != ONE_BITS);
                if (valid && pr[e] <= thr) {
                    lsum += -__logf(pr[e]);
                    cnt++;
                }
            }
        }
        __shared__ float shf[32];
        __shared__ unsigned int shu[32];
#pragma unroll
        for (int o = 16; o; o >>= 1) {
            lsum += __shfl_down_sync(0xffffffffu, lsum, o);
            cnt += __shfl_down_sync(0xffffffffu, cnt, o);
        }
        if (lane == 0) { shf[wid] = lsum; shu[wid] = cnt; }
        __syncthreads();
        if (t == 0) {
            double tot = 0.0;
            unsigned int ct = 0;
            for (int j = 0; j < 8; j++) { tot += (double)shf[j]; ct += shu[j]; }
            if (ct < 1u) ct = 1u;
            out[0] = (float)(tot / (double)ct);
        }
    }
}

// ---------------------------------------------------------------------------
extern "C" void kernel_launch(void* const* d_in, const int* in_sizes, int n_in,
                              void* d_out, int out_size) {
    const float* pred = (const float*)d_in[0];
    const int* target = (const int*)d_in[1];
    float* out = (float*)d_out;

    ohem_kernel<<<MAIN_BLOCKS, 256>>>(pred, target, out);
}

// round 11
// speedup vs baseline: 1.2642x; 1.2642x over previous
#include <cuda_runtime.h>

// Problem constants
#define BATCH 8
#define NCLS 19
#define HH 768
#define WW 768
#define HWP (HH * WW)                 // 589824
#define N_PIX (BATCH * HWP)           // 4718592
#define N4 (N_PIX / 4)                // 1179648
#define IGNORE_LBL 255
#define MIN_KEPT_K 262144u
#define THRESH_F 0.7f
#define ONE_BITS 0x3F800000u
#define ALMOST_ONE_BITS 0x3F7FFFFFu
#define MAIN_BLOCKS 1184
#define MAIN_STRIDE (MAIN_BLOCKS * 256)   // 303104 < HWP

// Scratch (no cudaMalloc allowed). Globals are zero at module load; each
// launch self-restores the state it consumes (replay-deterministic).
__device__ float g_prob[N_PIX];                // rare path only
__device__ unsigned int g_h16[65536];          // rare path only (zeroed there)
__device__ unsigned int g_skip;                // 1 = out written by main, 2 = refine
__device__ unsigned int g_num_valid;
__device__ unsigned int g_c07;
__device__ double g_sum07;
__device__ double g_sumall;
__device__ unsigned int g_done_main;

// ---------------------------------------------------------------------------
__device__ __forceinline__ float encode_prob(float logp, bool valid) {
    if (!valid) return 1.0f;
    float pr = __expf(logp);
    unsigned int bb = __float_as_uint(pr);
    if (bb >= ONE_BITS) bb = ALMOST_ONE_BITS;   // 1.0f bits reserved for invalid
    return __uint_as_float(bb);
}

__device__ __forceinline__ unsigned int scan256_shared(unsigned int* s) {
    int t = threadIdx.x;
#pragma unroll
    for (int o = 1; o < 256; o <<= 1) {
        unsigned int v = (t >= o) ? s[t - o] : 0u;
        __syncthreads();
        s[t] += v;
        __syncthreads();
    }
    return s[t];
}

// ---------------------------------------------------------------------------
// Main pass: fused log-softmax + common-path reductions. Lean register
// budget (min 6 CTAs/SM) — the rare path lives in a separate kernel so its
// register pressure cannot touch this loop.
__global__ void __launch_bounds__(256, 6) main_pass(const float* __restrict__ pred,
                                                    const int* __restrict__ target,
                                                    float* __restrict__ out) {
    unsigned int vcnt = 0, c07 = 0;
    float lsum07 = 0.0f, lsumall = 0.0f;

    int i0 = blockIdx.x * blockDim.x + threadIdx.x;
    int b = i0 / HWP;                  // single divide; then incremental carry
    int hw = i0 - b * HWP;

    for (int i = i0; i < N_PIX; i += MAIN_STRIDE) {
        int t = __ldcs(target + i);
        bool valid = (t != IGNORE_LBL);
        int tc = valid ? t : 0;

        const float* p = pred + (size_t)b * (NCLS * HWP) + hw;
        float s0 = 0.0f, s1 = 0.0f, s2 = 0.0f, s3 = 0.0f;
        float vt = 0.0f;
#pragma unroll
        for (int c = 0; c < NCLS; c++) {
            float x = __ldcs(p + c * HWP);
            if (c == tc) vt = x;          // predicated select, no dynamic indexing
            if ((c & 3) == 0) s0 += __expf(x);
            else if ((c & 3) == 1) s1 += __expf(x);
            else if ((c & 3) == 2) s2 += __expf(x);
            else s3 += __expf(x);
        }
        float logp = vt - __logf((s0 + s1) + (s2 + s3));   // logits bounded
        float pr = encode_prob(logp, valid);

        bool kept07 = valid && (pr <= THRESH_F);
        vcnt += valid ? 1u : 0u;
        c07  += kept07 ? 1u : 0u;
        lsumall += valid ? -logp : 0.0f;
        lsum07  += kept07 ? -logp : 0.0f;

        hw += MAIN_STRIDE;
        if (hw >= HWP) { hw -= HWP; b++; }
    }

    // block-reduce 2 uints + 2 floats
    __shared__ unsigned int sh[32], sh2[32];
    __shared__ float sf[32], sf2[32];
    int lane = threadIdx.x & 31, wid = threadIdx.x >> 5;
#pragma unroll
    for (int o = 16; o; o >>= 1) {
        vcnt += __shfl_down_sync(0xffffffffu, vcnt, o);
        c07  += __shfl_down_sync(0xffffffffu, c07, o);
        lsum07 += __shfl_down_sync(0xffffffffu, lsum07, o);
        lsumall += __shfl_down_sync(0xffffffffu, lsumall, o);
    }
    if (lane == 0) { sh[wid] = vcnt; sh2[wid] = c07; sf[wid] = lsum07; sf2[wid] = lsumall; }
    __syncthreads();
    if (wid == 0) {
        unsigned int v = (lane < 8) ? sh[lane] : 0u;
        unsigned int w = (lane < 8) ? sh2[lane] : 0u;
        float f1 = (lane < 8) ? sf[lane] : 0.0f;
        float f2 = (lane < 8) ? sf2[lane] : 0.0f;
#pragma unroll
        for (int o = 16; o; o >>= 1) {
            v += __shfl_down_sync(0xffffffffu, v, o);
            w += __shfl_down_sync(0xffffffffu, w, o);
            f1 += __shfl_down_sync(0xffffffffu, f1, o);
            f2 += __shfl_down_sync(0xffffffffu, f2, o);
        }
        if (lane == 0) {
            atomicAdd(&g_num_valid, v);
            atomicAdd(&g_c07, w);
            atomicAdd(&g_sum07, (double)f1);
            atomicAdd(&g_sumall, (double)f2);
        }
    }

    // last block: decide case, emit output (common) or flag the rare path.
    __shared__ bool is_last;
    if (threadIdx.x == 0) {
        __threadfence();
        is_last = (atomicAdd(&g_done_main, 1u) == gridDim.x - 1);
    }
    __syncthreads();
    if (is_last && threadIdx.x == 0) {
        unsigned int nv = g_num_valid;
        unsigned int c07v = g_c07;
        bool do_ohem = (nv >= MIN_KEPT_K);
        if (!do_ohem) {
            unsigned int d = nv < 1u ? 1u : nv;
            out[0] = (float)(g_sumall / (double)d);
            g_skip = 1u;
        } else if (c07v >= MIN_KEPT_K) {    // kth <= 0.7 => threshold == 0.7
            unsigned int d = c07v < 1u ? 1u : c07v;
            out[0] = (float)(g_sum07 / (double)d);
            g_skip = 1u;
        } else {
            g_skip = 2u;
        }
        g_num_valid = 0u; g_c07 = 0u;
        g_sum07 = 0.0; g_sumall = 0.0;
        g_done_main = 0u;
    }
}

// ---------------------------------------------------------------------------
// Rare path: SINGLE block (grid=1), correctness-only. Exact radix select over
// recomputed gt-probs + masked mean. Common case: read flag, exit (~2 us).
__global__ void __launch_bounds__(256) refine_1blk(const float* __restrict__ pred,
                                                   const int* __restrict__ target,
                                                   float* __restrict__ out) {
    if (g_skip == 1u) return;          // common case

    const int t = threadIdx.x;
    __shared__ unsigned int shh[256];

    // pass 1: recompute prob for all pixels, store, exponent hist
    shh[t] = 0u;
    __syncthreads();
    {
        int b = 0, hw = t;
        for (int i = t; i < N_PIX; i += 256) {
            int tg = target[i];
            bool valid = (tg != IGNORE_LBL);
            int tc = valid ? tg : 0;
            const float* p = pred + (size_t)b * (NCLS * HWP) + hw;
            float sa = 0.0f, sb = 0.0f;
            float vt = 0.0f;
#pragma unroll
            for (int c = 0; c < NCLS; c++) {
                float x = p[c * HWP];
                if (c == tc) vt = x;
                if (c & 1) sb += __expf(x); else sa += __expf(x);
            }
            float pr = encode_prob(vt - __logf(sa + sb), valid);
            g_prob[i] = pr;
            atomicAdd(&shh[__float_as_uint(pr) >> 24], 1u);
            hw += 256;
            if (hw >= HWP) { hw -= HWP; b++; }
        }
    }
    __syncthreads();

    // scan round 1 (bits 31..24)
    __shared__ unsigned int s_prefix, s_k;
    {
        unsigned int cc = shh[t];
        unsigned int incl = scan256_shared(shh);
        unsigned int excl = incl - cc;
        if (excl < MIN_KEPT_K && MIN_KEPT_K <= incl) {
            s_prefix = ((unsigned int)t) << 24;
            s_k = MIN_KEPT_K - excl;
        }
    }
    __syncthreads();

    // round 2: bits 23..8 filtered on hi-8 prefix (global 64K bins)
    for (int i = t; i < 65536; i += 256) g_h16[i] = 0u;
    __syncthreads();
    {
        unsigned int prefix = s_prefix;
        const uint4* p4u = reinterpret_cast<const uint4*>(g_prob);
        for (int i = t; i < N4; i += 256) {
            uint4 v = p4u[i];
            if ((v.x & 0xFF000000u) == prefix) atomicAdd(&g_h16[(v.x >> 8) & 0xFFFFu], 1u);
            if ((v.y & 0xFF000000u) == prefix) atomicAdd(&g_h16[(v.y >> 8) & 0xFFFFu], 1u);
            if ((v.z & 0xFF000000u) == prefix) atomicAdd(&g_h16[(v.z >> 8) & 0xFFFFu], 1u);
            if ((v.w & 0xFF000000u) == prefix) atomicAdd(&g_h16[(v.w >> 8) & 0xFFFFu], 1u);
        }
    }
    __syncthreads();
    {
        int base = t * 256;
        unsigned int lsum = 0;
        const uint4* h4 = reinterpret_cast<const uint4*>(g_h16);
        for (int j = 0; j < 64; j++) {
            uint4 u = h4[(base >> 2) + j];
            lsum += u.x + u.y + u.z + u.w;
        }
        shh[t] = lsum;
        __syncthreads();
        unsigned int incl = scan256_shared(shh);
        unsigned int excl = incl - lsum;
        unsigned int kk = s_k;
        if (excl < kk && kk <= incl && lsum > 0) {
            unsigned int cum = excl;
            for (int b2 = 0; b2 < 256; b2++) {
                unsigned int c = g_h16[base + b2];
                cum += c;
                if (cum >= kk) {
                    s_prefix = s_prefix | (((unsigned int)(base + b2)) << 8);
                    s_k = kk - (cum - c);
                    break;
                }
            }
        }
    }
    __syncthreads();

    // round 3: bits 7..0 filtered on hi-24 prefix
    __shared__ unsigned int s_kth;
    shh[t] = 0u;
    __syncthreads();
    {
        unsigned int prefix = s_prefix;
        const uint4* p4u = reinterpret_cast<const uint4*>(g_prob);
        for (int i = t; i < N4; i += 256) {
            uint4 v = p4u[i];
            if ((v.x & 0xFFFFFF00u) == prefix) atomicAdd(&shh[v.x & 255u], 1u);
            if ((v.y & 0xFFFFFF00u) == prefix) atomicAdd(&shh[v.y & 255u], 1u);
            if ((v.z & 0xFFFFFF00u) == prefix) atomicAdd(&shh[v.z & 255u], 1u);
            if ((v.w & 0xFFFFFF00u) == prefix) atomicAdd(&shh[v.w & 255u], 1u);
        }
    }
    __syncthreads();
    {
        unsigned int cc = shh[t];
        unsigned int incl = scan256_shared(shh);
        unsigned int excl = incl - cc;
        unsigned int kk = s_k;
        if (excl < kk && kk <= incl) {
            s_kth = s_prefix | (unsigned int)t;
        }
    }
    __syncthreads();

    // final reduce over g_prob (do_ohem true on this path)
    {
        float thr = fmaxf(__uint_as_float(s_kth), THRESH_F);
        float lsum = 0.0f;
        unsigned int cnt = 0;
        const float4* p4 = reinterpret_cast<const float4*>(g_prob);
        for (int i = t; i < N4; i += 256) {
            float4 v = p4[i];
            float pr[4] = {v.x, v.y, v.z, v.w};
#pragma unroll
            for (int e = 0; e < 4; e++) {
                bool valid = (__float_as_uint(pr[e]) != ONE_BITS);
                if (valid && pr[e] <= thr) {
                    lsum += -__logf(pr[e]);
                    cnt++;
                }
            }
        }
        __shared__ float shf[32];
        __shared__ unsigned int shu[32];
        int lane = t & 31, wid = t >> 5;
#pragma unroll
        for (int o = 16; o; o >>= 1) {
            lsum += __shfl_down_sync(0xffffffffu, lsum, o);
            cnt += __shfl_down_sync(0xffffffffu, cnt, o);
        }
        if (lane == 0) { shf[wid] = lsum; shu[wid] = cnt; }
        __syncthreads();
        if (t == 0) {
            double tot = 0.0;
            unsigned int ct = 0;
            for (int j = 0; j < 8; j++) { tot += (double)shf[j]; ct += shu[j]; }
            if (ct < 1u) ct = 1u;
            out[0] = (float)(tot / (double)ct);
        }
    }
}

// ---------------------------------------------------------------------------
extern "C" void kernel_launch(void* const* d_in, const int* in_sizes, int n_in,
                              void* d_out, int out_size) {
    const float* pred = (const float*)d_in[0];
    const int* target = (const int*)d_in[1];
    float* out = (float*)d_out;

    main_pass<<<MAIN_BLOCKS, 256>>>(pred, target, out);
    refine_1blk<<<1, 256>>>(pred, target, out);
}

// round 12
// speedup vs baseline: 1.4203x; 1.1235x over previous
#include <cuda_runtime.h>

// Problem constants
#define BATCH 8
#define NCLS 19
#define HH 768
#define WW 768
#define HWP (HH * WW)                 // 589824
#define N_PIX (BATCH * HWP)           // 4718592
#define N4 (N_PIX / 4)                // 1179648
#define IGNORE_LBL 255
#define MIN_KEPT_K 262144u
#define THRESH_F 0.7f
#define ONE_BITS 0x3F800000u
#define ALMOST_ONE_BITS 0x3F7FFFFFu
#define MAIN_BLOCKS 1184
#define MAIN_STRIDE (MAIN_BLOCKS * 256)   // 303104 < HWP

// Scratch (no cudaMalloc allowed). Globals are zero at module load; each
// launch self-restores the state it consumes (replay-deterministic).
__device__ float g_prob[N_PIX];                // rare path only
__device__ unsigned int g_h16[65536];          // rare path only (zeroed there)
__device__ unsigned int g_skip;                // 1 = out written by main, 2 = refine
__device__ unsigned int g_num_valid;
__device__ unsigned int g_c07;
__device__ double g_sum07;
__device__ double g_sumall;
__device__ unsigned int g_done_main;

// ---------------------------------------------------------------------------
__device__ __forceinline__ float encode_prob(float logp, bool valid) {
    if (!valid) return 1.0f;
    float pr = __expf(logp);
    unsigned int bb = __float_as_uint(pr);
    if (bb >= ONE_BITS) bb = ALMOST_ONE_BITS;   // 1.0f bits reserved for invalid
    return __uint_as_float(bb);
}

__device__ __forceinline__ unsigned int scan256_shared(unsigned int* s) {
    int t = threadIdx.x;
#pragma unroll
    for (int o = 1; o < 256; o <<= 1) {
        unsigned int v = (t >= o) ? s[t - o] : 0u;
        __syncthreads();
        s[t] += v;
        __syncthreads();
    }
    return s[t];
}

// ---------------------------------------------------------------------------
// Main pass (R9-proven form; NO launch-bounds min-blocks clause — forcing a
// register cap spilled and cost ~7 us in R11). Fused log-softmax +
// common-path reductions; last block writes the scalar in the common case.
__global__ void __launch_bounds__(256) main_pass(const float* __restrict__ pred,
                                                 const int* __restrict__ target,
                                                 float* __restrict__ out) {
#if (__CUDA_ARCH__ >= 900)
    cudaTriggerProgrammaticLaunchCompletion();   // PDL: let refine launch early
#endif

    unsigned int vcnt = 0, c07 = 0;
    float lsum07 = 0.0f, lsumall = 0.0f;

    int i0 = blockIdx.x * blockDim.x + threadIdx.x;
    int b = i0 / HWP;                  // single divide; then incremental carry
    int hw = i0 - b * HWP;

    for (int i = i0; i < N_PIX; i += MAIN_STRIDE) {
        int t = __ldcs(target + i);
        bool valid = (t != IGNORE_LBL);
        int tc = valid ? t : 0;

        const float* p = pred + (size_t)b * (NCLS * HWP) + hw;
        float s0 = 0.0f, s1 = 0.0f, s2 = 0.0f, s3 = 0.0f;
        float vt = 0.0f;
#pragma unroll
        for (int c = 0; c < NCLS; c++) {
            float x = __ldcs(p + c * HWP);
            if (c == tc) vt = x;          // predicated select, no dynamic indexing
            if ((c & 3) == 0) s0 += __expf(x);
            else if ((c & 3) == 1) s1 += __expf(x);
            else if ((c & 3) == 2) s2 += __expf(x);
            else s3 += __expf(x);
        }
        float logp = vt - __logf((s0 + s1) + (s2 + s3));   // logits bounded
        float pr = encode_prob(logp, valid);

        bool kept07 = valid && (pr <= THRESH_F);
        vcnt += valid ? 1u : 0u;
        c07  += kept07 ? 1u : 0u;
        lsumall += valid ? -logp : 0.0f;
        lsum07  += kept07 ? -logp : 0.0f;

        hw += MAIN_STRIDE;
        if (hw >= HWP) { hw -= HWP; b++; }
    }

    // block-reduce 2 uints + 2 floats
    __shared__ unsigned int sh[32], sh2[32];
    __shared__ float sf[32], sf2[32];
    int lane = threadIdx.x & 31, wid = threadIdx.x >> 5;
#pragma unroll
    for (int o = 16; o; o >>= 1) {
        vcnt += __shfl_down_sync(0xffffffffu, vcnt, o);
        c07  += __shfl_down_sync(0xffffffffu, c07, o);
        lsum07 += __shfl_down_sync(0xffffffffu, lsum07, o);
        lsumall += __shfl_down_sync(0xffffffffu, lsumall, o);
    }
    if (lane == 0) { sh[wid] = vcnt; sh2[wid] = c07; sf[wid] = lsum07; sf2[wid] = lsumall; }
    __syncthreads();
    if (wid == 0) {
        unsigned int v = (lane < 8) ? sh[lane] : 0u;
        unsigned int w = (lane < 8) ? sh2[lane] : 0u;
        float f1 = (lane < 8) ? sf[lane] : 0.0f;
        float f2 = (lane < 8) ? sf2[lane] : 0.0f;
#pragma unroll
        for (int o = 16; o; o >>= 1) {
            v += __shfl_down_sync(0xffffffffu, v, o);
            w += __shfl_down_sync(0xffffffffu, w, o);
            f1 += __shfl_down_sync(0xffffffffu, f1, o);
            f2 += __shfl_down_sync(0xffffffffu, f2, o);
        }
        if (lane == 0) {
            atomicAdd(&g_num_valid, v);
            atomicAdd(&g_c07, w);
            atomicAdd(&g_sum07, (double)f1);
            atomicAdd(&g_sumall, (double)f2);
        }
    }

    // last block: decide case, emit output (common) or flag the rare path.
    __shared__ bool is_last;
    if (threadIdx.x == 0) {
        __threadfence();
        is_last = (atomicAdd(&g_done_main, 1u) == gridDim.x - 1);
    }
    __syncthreads();
    if (is_last && threadIdx.x == 0) {
        unsigned int nv = g_num_valid;
        unsigned int c07v = g_c07;
        bool do_ohem = (nv >= MIN_KEPT_K);
        if (!do_ohem) {
            unsigned int d = nv < 1u ? 1u : nv;
            out[0] = (float)(g_sumall / (double)d);
            g_skip = 1u;
        } else if (c07v >= MIN_KEPT_K) {    // kth <= 0.7 => threshold == 0.7
            unsigned int d = c07v < 1u ? 1u : c07v;
            out[0] = (float)(g_sum07 / (double)d);
            g_skip = 1u;
        } else {
            g_skip = 2u;
        }
        g_num_valid = 0u; g_c07 = 0u;
        g_sum07 = 0.0; g_sumall = 0.0;
        g_done_main = 0u;
    }
}

// ---------------------------------------------------------------------------
// Rare path: SINGLE block, correctness-only. PDL: launch latency hides under
// main_pass's tail; cudaGridDependencySynchronize guarantees main's writes
// (incl. g_skip) are visible before the flag read.
__global__ void __launch_bounds__(256) refine_1blk(const float* __restrict__ pred,
                                                   const int* __restrict__ target,
                                                   float* __restrict__ out) {
#if (__CUDA_ARCH__ >= 900)
    cudaGridDependencySynchronize();   // blocks until main_pass fully retired
#endif
    if (g_skip == 1u) return;          // common case

    const int t = threadIdx.x;
    __shared__ unsigned int shh[256];

    // pass 1: recompute prob for all pixels, store, exponent hist
    shh[t] = 0u;
    __syncthreads();
    {
        int b = 0, hw = t;
        for (int i = t; i < N_PIX; i += 256) {
            int tg = target[i];
            bool valid = (tg != IGNORE_LBL);
            int tc = valid ? tg : 0;
            const float* p = pred + (size_t)b * (NCLS * HWP) + hw;
            float sa = 0.0f, sb = 0.0f;
            float vt = 0.0f;
#pragma unroll
            for (int c = 0; c < NCLS; c++) {
                float x = p[c * HWP];
                if (c == tc) vt = x;
                if (c & 1) sb += __expf(x); else sa += __expf(x);
            }
            float pr = encode_prob(vt - __logf(sa + sb), valid);
            g_prob[i] = pr;
            atomicAdd(&shh[__float_as_uint(pr) >> 24], 1u);
            hw += 256;
            if (hw >= HWP) { hw -= HWP; b++; }
        }
    }
    __syncthreads();

    // scan round 1 (bits 31..24)
    __shared__ unsigned int s_prefix, s_k;
    {
        unsigned int cc = shh[t];
        unsigned int incl = scan256_shared(shh);
        unsigned int excl = incl - cc;
        if (excl < MIN_KEPT_K && MIN_KEPT_K <= incl) {
            s_prefix = ((unsigned int)t) << 24;
            s_k = MIN_KEPT_K - excl;
        }
    }
    __syncthreads();

    // round 2: bits 23..8 filtered on hi-8 prefix (global 64K bins)
    for (int i = t; i < 65536; i += 256) g_h16[i] = 0u;
    __syncthreads();
    {
        unsigned int prefix = s_prefix;
        const uint4* p4u = reinterpret_cast<const uint4*>(g_prob);
        for (int i = t; i < N4; i += 256) {
            uint4 v = p4u[i];
            if ((v.x & 0xFF000000u) == prefix) atomicAdd(&g_h16[(v.x >> 8) & 0xFFFFu], 1u);
            if ((v.y & 0xFF000000u) == prefix) atomicAdd(&g_h16[(v.y >> 8) & 0xFFFFu], 1u);
            if ((v.z & 0xFF000000u) == prefix) atomicAdd(&g_h16[(v.z >> 8) & 0xFFFFu], 1u);
            if ((v.w & 0xFF000000u) == prefix) atomicAdd(&g_h16[(v.w >> 8) & 0xFFFFu], 1u);
        }
    }
    __syncthreads();
    {
        int base = t * 256;
        unsigned int lsum = 0;
        const uint4* h4 = reinterpret_cast<const uint4*>(g_h16);
        for (int j = 0; j < 64; j++) {
            uint4 u = h4[(base >> 2) + j];
            lsum += u.x + u.y + u.z + u.w;
        }
        shh[t] = lsum;
        __syncthreads();
        unsigned int incl = scan256_shared(shh);
        unsigned int excl = incl - lsum;
        unsigned int kk = s_k;
        if (excl < kk && kk <= incl && lsum > 0) {
            unsigned int cum = excl;
            for (int b2 = 0; b2 < 256; b2++) {
                unsigned int c = g_h16[base + b2];
                cum += c;
                if (cum >= kk) {
                    s_prefix = s_prefix | (((unsigned int)(base + b2)) << 8);
                    s_k = kk - (cum - c);
                    break;
                }
            }
        }
    }
    __syncthreads();

    // round 3: bits 7..0 filtered on hi-24 prefix
    __shared__ unsigned int s_kth;
    shh[t] = 0u;
    __syncthreads();
    {
        unsigned int prefix = s_prefix;
        const uint4* p4u = reinterpret_cast<const uint4*>(g_prob);
        for (int i = t; i < N4; i += 256) {
            uint4 v = p4u[i];
            if ((v.x & 0xFFFFFF00u) == prefix) atomicAdd(&shh[v.x & 255u], 1u);
            if ((v.y & 0xFFFFFF00u) == prefix) atomicAdd(&shh[v.y & 255u], 1u);
            if ((v.z & 0xFFFFFF00u) == prefix) atomicAdd(&shh[v.z & 255u], 1u);
            if ((v.w & 0xFFFFFF00u) == prefix) atomicAdd(&shh[v.w & 255u], 1u);
        }
    }
    __syncthreads();
    {
        unsigned int cc = shh[t];
        unsigned int incl = scan256_shared(shh);
        unsigned int excl = incl - cc;
        unsigned int kk = s_k;
        if (excl < kk && kk <= incl) {
            s_kth = s_prefix | (unsigned int)t;
        }
    }
    __syncthreads();

    // final reduce over g_prob (do_ohem true on this path)
    {
        float thr = fmaxf(__uint_as_float(s_kth), THRESH_F);
        float lsum = 0.0f;
        unsigned int cnt = 0;
        const float4* p4 = reinterpret_cast<const float4*>(g_prob);
        for (int i = t; i < N4; i += 256) {
            float4 v = p4[i];
            float pr[4] = {v.x, v.y, v.z, v.w};
#pragma unroll
            for (int e = 0; e < 4; e++) {
                bool valid = (__float_as_uint(pr[e]) != ONE_BITS);
                if (valid && pr[e] <= thr) {
                    lsum += -__logf(pr[e]);
                    cnt++;
                }
            }
        }
        __shared__ float shf[32];
        __shared__ unsigned int shu[32];
        int lane = t & 31, wid = t >> 5;
#pragma unroll
        for (int o = 16; o; o >>= 1) {
            lsum += __shfl_down_sync(0xffffffffu, lsum, o);
            cnt += __shfl_down_sync(0xffffffffu, cnt, o);
        }
        if (lane == 0) { shf[wid] = lsum; shu[wid] = cnt; }
        __syncthreads();
        if (t == 0) {
            double tot = 0.0;
            unsigned int ct = 0;
            for (int j = 0; j < 8; j++) { tot += (double)shf[j]; ct += shu[j]; }
            if (ct < 1u) ct = 1u;
            out[0] = (float)(tot / (double)ct);
        }
    }
}

// ---------------------------------------------------------------------------
extern "C" void kernel_launch(void* const* d_in, const int* in_sizes, int n_in,
                              void* d_out, int out_size) {
    const float* pred = (const float*)d_in[0];
    const int* target = (const int*)d_in[1];
    float* out = (float*)d_out;

    main_pass<<<MAIN_BLOCKS, 256>>>(pred, target, out);

    // PDL: refine_1blk's ~4 us launch latency overlaps main_pass's tail.
    cudaLaunchConfig_t cfg = {};
    cfg.gridDim = dim3(1, 1, 1);
    cfg.blockDim = dim3(256, 1, 1);
    cfg.dynamicSmemBytes = 0;
    cfg.stream = 0;
    cudaLaunchAttribute attrs[1];
    attrs[0].id = cudaLaunchAttributeProgrammaticStreamSerialization;
    attrs[0].val.programmaticStreamSerializationAllowed = 1;
    cfg.attrs = attrs;
    cfg.numAttrs = 1;
    cudaLaunchKernelEx(&cfg, refine_1blk, pred, target, out);
}

// round 13
// speedup vs baseline: 1.5158x; 1.0672x over previous
#include <cuda_runtime.h>

// Problem constants
#define BATCH 8
#define NCLS 19
#define HH 768
#define WW 768
#define HWP (HH * WW)                 // 589824
#define HWP2 (HWP / 2)                // 294912
#define N_PIX (BATCH * HWP)           // 4718592
#define N4 (N_PIX / 4)                // 1179648
#define IGNORE_LBL 255
#define MIN_KEPT_K 262144u
#define THRESH_F 0.7f
#define ONE_BITS 0x3F800000u
#define ALMOST_ONE_BITS 0x3F7FFFFFu
#define MAIN_BLOCKS 1152              // 1152*256 == HWP/2 exactly
#define RF_BLOCKS 1

// Scratch (no cudaMalloc allowed). Globals are zero at module load; each
// launch self-restores the state it consumes (replay-deterministic).
__device__ float g_prob[N_PIX];                // rare path only
__device__ unsigned int g_h16[65536];          // rare path only (zeroed there)
__device__ unsigned int g_skip;                // 1 = out written by main, 2 = refine
__device__ unsigned int g_num_valid;
__device__ unsigned int g_c07;
__device__ double g_sum07;
__device__ double g_sumall;
__device__ unsigned int g_done_main;

// ---------------------------------------------------------------------------
__device__ __forceinline__ float encode_prob(float logp, bool valid) {
    if (!valid) return 1.0f;
    float pr = __expf(logp);
    unsigned int bb = __float_as_uint(pr);
    if (bb >= ONE_BITS) bb = ALMOST_ONE_BITS;   // 1.0f bits reserved for invalid
    return __uint_as_float(bb);
}

__device__ __forceinline__ unsigned int scan256_shared(unsigned int* s) {
    int t = threadIdx.x;
#pragma unroll
    for (int o = 1; o < 256; o <<= 1) {
        unsigned int v = (t >= o) ? s[t - o] : 0u;
        __syncthreads();
        s[t] += v;
        __syncthreads();
    }
    return s[t];
}

// ---------------------------------------------------------------------------
// Main pass: float2 (2 pixels/thread). Batch loop is NOT unrolled
// (`#pragma unroll 1` — R8's full unroll spilled); only the 19-channel
// inner loop unrolls. hw2 is loop-invariant: zero index math per iteration.
__global__ void __launch_bounds__(256) main_pass(const float* __restrict__ pred,
                                                 const int* __restrict__ target,
                                                 float* __restrict__ out) {
#if (__CUDA_ARCH__ >= 900)
    cudaTriggerProgrammaticLaunchCompletion();   // PDL: let refine launch early
#endif

    const int hw2 = blockIdx.x * blockDim.x + threadIdx.x;   // < HWP2 by grid sizing

    unsigned int vcnt = 0, c07 = 0;
    float lsum07 = 0.0f, lsumall = 0.0f;

#pragma unroll 1
    for (int b = 0; b < BATCH; b++) {
        int2 tt = __ldcs(reinterpret_cast<const int2*>(target) + b * HWP2 + hw2);
        bool v0 = (tt.x != IGNORE_LBL);
        bool v1 = (tt.y != IGNORE_LBL);
        int tc0 = v0 ? tt.x : 0;
        int tc1 = v1 ? tt.y : 0;

        const float2* p = reinterpret_cast<const float2*>(pred)
                          + (size_t)b * NCLS * HWP2 + hw2;
        float s00 = 0.0f, s01 = 0.0f, s10 = 0.0f, s11 = 0.0f;
        float vt0 = 0.0f, vt1 = 0.0f;
#pragma unroll
        for (int c = 0; c < NCLS; c++) {
            float2 x = __ldcs(p + c * HWP2);
            if (c == tc0) vt0 = x.x;      // predicated selects, no dynamic indexing
            if (c == tc1) vt1 = x.y;
            if (c & 1) { s01 += __expf(x.x); s11 += __expf(x.y); }
            else       { s00 += __expf(x.x); s10 += __expf(x.y); }
        }
        float l0 = vt0 - __logf(s00 + s01);   // logits bounded: no max-subtract
        float l1 = vt1 - __logf(s10 + s11);
        float pr0 = encode_prob(l0, v0);
        float pr1 = encode_prob(l1, v1);

        bool k0 = v0 && (pr0 <= THRESH_F);
        bool k1 = v1 && (pr1 <= THRESH_F);
        vcnt += (v0 ? 1u : 0u) + (v1 ? 1u : 0u);
        c07  += (k0 ? 1u : 0u) + (k1 ? 1u : 0u);
        lsumall += (v0 ? -l0 : 0.0f) + (v1 ? -l1 : 0.0f);
        lsum07  += (k0 ? -l0 : 0.0f) + (k1 ? -l1 : 0.0f);
    }

    // block-reduce 2 uints + 2 floats
    __shared__ unsigned int sh[32], sh2[32];
    __shared__ float sf[32], sf2[32];
    int lane = threadIdx.x & 31, wid = threadIdx.x >> 5;
#pragma unroll
    for (int o = 16; o; o >>= 1) {
        vcnt += __shfl_down_sync(0xffffffffu, vcnt, o);
        c07  += __shfl_down_sync(0xffffffffu, c07, o);
        lsum07 += __shfl_down_sync(0xffffffffu, lsum07, o);
        lsumall += __shfl_down_sync(0xffffffffu, lsumall, o);
    }
    if (lane == 0) { sh[wid] = vcnt; sh2[wid] = c07; sf[wid] = lsum07; sf2[wid] = lsumall; }
    __syncthreads();
    if (wid == 0) {
        unsigned int v = (lane < 8) ? sh[lane] : 0u;
        unsigned int w = (lane < 8) ? sh2[lane] : 0u;
        float f1 = (lane < 8) ? sf[lane] : 0.0f;
        float f2 = (lane < 8) ? sf2[lane] : 0.0f;
#pragma unroll
        for (int o = 16; o; o >>= 1) {
            v += __shfl_down_sync(0xffffffffu, v, o);
            w += __shfl_down_sync(0xffffffffu, w, o);
            f1 += __shfl_down_sync(0xffffffffu, f1, o);
            f2 += __shfl_down_sync(0xffffffffu, f2, o);
        }
        if (lane == 0) {
            atomicAdd(&g_num_valid, v);
            atomicAdd(&g_c07, w);
            atomicAdd(&g_sum07, (double)f1);
            atomicAdd(&g_sumall, (double)f2);
        }
    }

    // last block: decide case, emit output (common) or flag the rare path.
    __shared__ bool is_last;
    if (threadIdx.x == 0) {
        __threadfence();
        is_last = (atomicAdd(&g_done_main, 1u) == gridDim.x - 1);
    }
    __syncthreads();
    if (is_last && threadIdx.x == 0) {
        unsigned int nv = g_num_valid;
        unsigned int c07v = g_c07;
        bool do_ohem = (nv >= MIN_KEPT_K);
        if (!do_ohem) {
            unsigned int d = nv < 1u ? 1u : nv;
            out[0] = (float)(g_sumall / (double)d);
            g_skip = 1u;
        } else if (c07v >= MIN_KEPT_K) {    // kth <= 0.7 => threshold == 0.7
            unsigned int d = c07v < 1u ? 1u : c07v;
            out[0] = (float)(g_sum07 / (double)d);
            g_skip = 1u;
        } else {
            g_skip = 2u;
        }
        g_num_valid = 0u; g_c07 = 0u;
        g_sum07 = 0.0; g_sumall = 0.0;
        g_done_main = 0u;
    }
}

// ---------------------------------------------------------------------------
// Rare path: SINGLE block, correctness-only (identical to R12).
__global__ void __launch_bounds__(256) refine_1blk(const float* __restrict__ pred,
                                                   const int* __restrict__ target,
                                                   float* __restrict__ out) {
#if (__CUDA_ARCH__ >= 900)
    cudaGridDependencySynchronize();   // blocks until main_pass fully retired
#endif
    if (g_skip == 1u) return;          // common case

    const int t = threadIdx.x;
    __shared__ unsigned int shh[256];

    // pass 1: recompute prob for all pixels, store, exponent hist
    shh[t] = 0u;
    __syncthreads();
    {
        int b = 0, hw = t;
        for (int i = t; i < N_PIX; i += 256) {
            int tg = target[i];
            bool valid = (tg != IGNORE_LBL);
            int tc = valid ? tg : 0;
            const float* p = pred + (size_t)b * (NCLS * HWP) + hw;
            float sa = 0.0f, sb = 0.0f;
            float vt = 0.0f;
#pragma unroll
            for (int c = 0; c < NCLS; c++) {
                float x = p[c * HWP];
                if (c == tc) vt = x;
                if (c & 1) sb += __expf(x); else sa += __expf(x);
            }
            float pr = encode_prob(vt - __logf(sa + sb), valid);
            g_prob[i] = pr;
            atomicAdd(&shh[__float_as_uint(pr) >> 24], 1u);
            hw += 256;
            if (hw >= HWP) { hw -= HWP; b++; }
        }
    }
    __syncthreads();

    // scan round 1 (bits 31..24)
    __shared__ unsigned int s_prefix, s_k;
    {
        unsigned int cc = shh[t];
        unsigned int incl = scan256_shared(shh);
        unsigned int excl = incl - cc;
        if (excl < MIN_KEPT_K && MIN_KEPT_K <= incl) {
            s_prefix = ((unsigned int)t) << 24;
            s_k = MIN_KEPT_K - excl;
        }
    }
    __syncthreads();

    // round 2: bits 23..8 filtered on hi-8 prefix (global 64K bins)
    for (int i = t; i < 65536; i += 256) g_h16[i] = 0u;
    __syncthreads();
    {
        unsigned int prefix = s_prefix;
        const uint4* p4u = reinterpret_cast<const uint4*>(g_prob);
        for (int i = t; i < N4; i += 256) {
            uint4 v = p4u[i];
            if ((v.x & 0xFF000000u) == prefix) atomicAdd(&g_h16[(v.x >> 8) & 0xFFFFu], 1u);
            if ((v.y & 0xFF000000u) == prefix) atomicAdd(&g_h16[(v.y >> 8) & 0xFFFFu], 1u);
            if ((v.z & 0xFF000000u) == prefix) atomicAdd(&g_h16[(v.z >> 8) & 0xFFFFu], 1u);
            if ((v.w & 0xFF000000u) == prefix) atomicAdd(&g_h16[(v.w >> 8) & 0xFFFFu], 1u);
        }
    }
    __syncthreads();
    {
        int base = t * 256;
        unsigned int lsum = 0;
        const uint4* h4 = reinterpret_cast<const uint4*>(g_h16);
        for (int j = 0; j < 64; j++) {
            uint4 u = h4[(base >> 2) + j];
            lsum += u.x + u.y + u.z + u.w;
        }
        shh[t] = lsum;
        __syncthreads();
        unsigned int incl = scan256_shared(shh);
        unsigned int excl = incl - lsum;
        unsigned int kk = s_k;
        if (excl < kk && kk <= incl && lsum > 0) {
            unsigned int cum = excl;
            for (int b2 = 0; b2 < 256; b2++) {
                unsigned int c = g_h16[base + b2];
                cum += c;
                if (cum >= kk) {
                    s_prefix = s_prefix | (((unsigned int)(base + b2)) << 8);
                    s_k = kk - (cum - c);
                    break;
                }
            }
        }
    }
    __syncthreads();

    // round 3: bits 7..0 filtered on hi-24 prefix
    __shared__ unsigned int s_kth;
    shh[t] = 0u;
    __syncthreads();
    {
        unsigned int prefix = s_prefix;
        const uint4* p4u = reinterpret_cast<const uint4*>(g_prob);
        for (int i = t; i < N4; i += 256) {
            uint4 v = p4u[i];
            if ((v.x & 0xFFFFFF00u) == prefix) atomicAdd(&shh[v.x & 255u], 1u);
            if ((v.y & 0xFFFFFF00u) == prefix) atomicAdd(&shh[v.y & 255u], 1u);
            if ((v.z & 0xFFFFFF00u) == prefix) atomicAdd(&shh[v.z & 255u], 1u);
            if ((v.w & 0xFFFFFF00u) == prefix) atomicAdd(&shh[v.w & 255u], 1u);
        }
    }
    __syncthreads();
    {
        unsigned int cc = shh[t];
        unsigned int incl = scan256_shared(shh);
        unsigned int excl = incl - cc;
        unsigned int kk = s_k;
        if (excl < kk && kk <= incl) {
            s_kth = s_prefix | (unsigned int)t;
        }
    }
    __syncthreads();

    // final reduce over g_prob (do_ohem true on this path)
    {
        float thr = fmaxf(__uint_as_float(s_kth), THRESH_F);
        float lsum = 0.0f;
        unsigned int cnt = 0;
        const float4* p4 = reinterpret_cast<const float4*>(g_prob);
        for (int i = t; i < N4; i += 256) {
            float4 v = p4[i];
            float pr[4] = {v.x, v.y, v.z, v.w};
#pragma unroll
            for (int e = 0; e < 4; e++) {
                bool valid = (__float_as_uint(pr[e]) != ONE_BITS);
                if (valid && pr[e] <= thr) {
                    lsum += -__logf(pr[e]);
                    cnt++;
                }
            }
        }
        __shared__ float shf[32];
        __shared__ unsigned int shu[32];
        int lane = t & 31, wid = t >> 5;
#pragma unroll
        for (int o = 16; o; o >>= 1) {
            lsum += __shfl_down_sync(0xffffffffu, lsum, o);
            cnt += __shfl_down_sync(0xffffffffu, cnt, o);
        }
        if (lane == 0) { shf[wid] = lsum; shu[wid] = cnt; }
        __syncthreads();
        if (t == 0) {
            double tot = 0.0;
            unsigned int ct = 0;
            for (int j = 0; j < 8; j++) { tot += (double)shf[j]; ct += shu[j]; }
            if (ct < 1u) ct = 1u;
            out[0] = (float)(tot / (double)ct);
        }
    }
}

// ---------------------------------------------------------------------------
extern "C" void kernel_launch(void* const* d_in, const int* in_sizes, int n_in,
                              void* d_out, int out_size) {
    const float* pred = (const float*)d_in[0];
    const int* target = (const int*)d_in[1];
    float* out = (float*)d_out;

    main_pass<<<MAIN_BLOCKS, 256>>>(pred, target, out);

    // PDL: refine_1blk's launch latency overlaps main_pass's tail.
    cudaLaunchConfig_t cfg = {};
    cfg.gridDim = dim3(RF_BLOCKS, 1, 1);
    cfg.blockDim = dim3(256, 1, 1);
    cfg.dynamicSmemBytes = 0;
    cfg.stream = 0;
    cudaLaunchAttribute attrs[1];
    attrs[0].id = cudaLaunchAttributeProgrammaticStreamSerialization;
    attrs[0].val.programmaticStreamSerializationAllowed = 1;
    cfg.attrs = attrs;
    cfg.numAttrs = 1;
    cudaLaunchKernelEx(&cfg, refine_1blk, pred, target, out);
}